// round 11
// baseline (speedup 1.0000x reference)
#include <cuda_runtime.h>
#include <cuda_bf16.h>

#define NN    65536
#define BG    64
#define NPG   1024
#define DD    512
#define DEG   32
#define EPG   (NPG*DEG)
#define EE    (BG*EPG)
#define DROPK 512
#define SPLIT 8                  // split-CTAs per graph for edge passes
#define NSPLITB (BG*SPLIT)       // 512
#define ECTA  (EPG/SPLIT)        // 4096 edges per split block

// Device scratch (no allocation allowed)
__device__ float g_h[NN];
__device__ int   g_deg_part[NSPLITB * NPG];
__device__ float g_agg[NN];
__device__ float g_wb[NN];

// int64 vs int32 edge-word probe (3 odd-word reads; L2-hot after first block).
__device__ __forceinline__ bool edges_are_i64(const unsigned int* p) {
    return (p[32769] == 0u) && (p[98305] == 0u) && (p[163841] == 0u);
}

// ---------------------------------------------------------------------------
// K1: fused. Blocks [0,512): per-split in-degree histograms + zero a 128-float
// slice of g_agg for this replay. Blocks [512, 512+4096): matvec h = feat @ w,
// two rows per warp. Deg's ATOMS work hides under the matvec DRAM stream.
// ---------------------------------------------------------------------------
__global__ __launch_bounds__(256) void k1_deg_matvec(
    const float4* __restrict__ feat, const float4* __restrict__ w,
    const void* __restrict__ dst_p, const unsigned int* __restrict__ src_raw)
{
    __shared__ __align__(16) unsigned char sm_raw[NPG * 4];   // 4 KB

    if (blockIdx.x < NSPLITB) {
        int* deg_s = (int*)sm_raw;
        const int tid = threadIdx.x;
        if (tid < 128) g_agg[blockIdx.x * 128 + tid] = 0.f;   // zero agg slice
        const bool is64 = edges_are_i64(src_raw);
        #pragma unroll
        for (int r = 0; r < 4; r++) deg_s[r * 256 + tid] = 0;
        __syncthreads();
        const long ebase = (long)blockIdx.x * ECTA;
        #pragma unroll
        for (int r = 0; r < ECTA / 256; r++) {      // 16 iters
            long e = ebase + r * 256 + tid;
            int d = is64 ? ((const int2*)dst_p)[e].x
                         : ((const int*)dst_p)[e];
            atomicAdd(&deg_s[d & (NPG - 1)], 1);
        }
        __syncthreads();
        int* part = g_deg_part + (size_t)blockIdx.x * NPG;
        #pragma unroll
        for (int r = 0; r < 4; r++) {
            int i = r * 256 + tid;
            part[i] = deg_s[i];
        }
    } else {
        float4* w_s = (float4*)sm_raw;              // 128 float4 = 2 KB
        if (threadIdx.x < DD / 4)
            w_s[threadIdx.x] = w[threadIdx.x];
        __syncthreads();

        int warp  = ((blockIdx.x - NSPLITB) * 256 + threadIdx.x) >> 5;
        int lane  = threadIdx.x & 31;
        int row0i = warp * 2;
        const float4* row0 = feat + (size_t)row0i * (DD / 4);
        const float4* row1 = row0 + (DD / 4);

        float4 a0 = row0[lane];      float4 a1 = row0[lane + 32];
        float4 a2 = row0[lane + 64]; float4 a3 = row0[lane + 96];
        float4 b0 = row1[lane];      float4 b1 = row1[lane + 32];
        float4 b2 = row1[lane + 64]; float4 b3 = row1[lane + 96];

        float4 w0 = w_s[lane];      float4 w1 = w_s[lane + 32];
        float4 w2 = w_s[lane + 64]; float4 w3 = w_s[lane + 96];

        float s0 = a0.x*w0.x + a0.y*w0.y + a0.z*w0.z + a0.w*w0.w
                 + a1.x*w1.x + a1.y*w1.y + a1.z*w1.z + a1.w*w1.w
                 + a2.x*w2.x + a2.y*w2.y + a2.z*w2.z + a2.w*w2.w
                 + a3.x*w3.x + a3.y*w3.y + a3.z*w3.z + a3.w*w3.w;
        float s1 = b0.x*w0.x + b0.y*w0.y + b0.z*w0.z + b0.w*w0.w
                 + b1.x*w1.x + b1.y*w1.y + b1.z*w1.z + b1.w*w1.w
                 + b2.x*w2.x + b2.y*w2.y + b2.z*w2.z + b2.w*w2.w
                 + b3.x*w3.x + b3.y*w3.y + b3.z*w3.z + b3.w*w3.w;
        #pragma unroll
        for (int o = 16; o; o >>= 1) {
            s0 += __shfl_down_sync(0xFFFFFFFFu, s0, o);
            s1 += __shfl_down_sync(0xFFFFFFFFu, s1, o);
        }
        if (lane == 0) {
            g_h[row0i]     = s0;
            g_h[row0i + 1] = s1;
        }
    }
}

// ---------------------------------------------------------------------------
// K2: scatter via direct no-return global atomics (REDG). 512 blocks x 1024
// threads (8 per graph, 4096 edges each). Reconstruct hn into shared, batch
// edge loads, then REDG g_agg[dst] += hn_s[src_local]. No partial writeback.
// ---------------------------------------------------------------------------
__global__ __launch_bounds__(1024) void k2_scatter(
    const void* __restrict__ src_p, const void* __restrict__ dst_p,
    const unsigned int* __restrict__ src_raw)
{
    __shared__ float hn_s[NPG];
    const int tid = threadIdx.x;
    const int g   = blockIdx.x >> 3;            // SPLIT = 8
    const bool is64 = edges_are_i64(src_raw);

    {
        int dg = 0;
        #pragma unroll
        for (int s = 0; s < SPLIT; s++)
            dg += g_deg_part[(size_t)(g * SPLIT + s) * NPG + tid];
        float h = g_h[g * NPG + tid];
        hn_s[tid] = (dg > 0) ? h * rsqrtf((float)dg) : 0.f;
    }
    __syncthreads();

    const long ebase = (long)blockIdx.x * ECTA;
    const int  nbase = g * NPG;
    int sv[ECTA / NPG], dv[ECTA / NPG];
    if (is64) {
        #pragma unroll
        for (int r = 0; r < ECTA / NPG; r++) {
            long e = ebase + r * NPG + tid;
            sv[r] = ((const int2*)src_p)[e].x;
            dv[r] = ((const int2*)dst_p)[e].x;
        }
    } else {
        #pragma unroll
        for (int r = 0; r < ECTA / NPG; r++) {
            long e = ebase + r * NPG + tid;
            sv[r] = ((const int*)src_p)[e];
            dv[r] = ((const int*)dst_p)[e];
        }
    }
    #pragma unroll
    for (int r = 0; r < ECTA / NPG; r++) {
        // no-return global atomic (REDG): result unused
        atomicAdd(&g_agg[nbase + (dv[r] & (NPG - 1))],
                  hn_s[sv[r] & (NPG - 1)]);
    }
}

// ---------------------------------------------------------------------------
// K3: finalize per graph: agg read directly, deg from partials,
// w = relu(agg*norm + bias), hybrid bitonic, threshold mask -> wb.
// ---------------------------------------------------------------------------
__global__ __launch_bounds__(1024) void k3_finalize(const float* __restrict__ bias)
{
    __shared__ float sort_s[NPG];
    __shared__ float w_s[NPG];
    __shared__ int   c_sh;

    const int g   = blockIdx.x;
    const int tid = threadIdx.x;
    const int i   = g * NPG + tid;

    int dg = 0;
    #pragma unroll
    for (int s = 0; s < SPLIT; s++)
        dg += g_deg_part[(size_t)(g * SPLIT + s) * NPG + tid];
    float agg = g_agg[i];
    float nm  = (dg > 0) ? rsqrtf((float)dg) : 0.f;
    float w   = fmaxf(agg * nm + bias[0], 0.f);
    w_s[tid] = w;
    float v  = w;

    // Bitonic sort ascending; shared only for cross-warp stages.
    for (int k = 2; k <= NPG; k <<= 1) {
        bool dir_up = ((tid & k) == 0);
        for (int j = k >> 1; j >= 32; j >>= 1) {
            sort_s[tid] = v;
            __syncthreads();
            float other = sort_s[tid ^ j];
            __syncthreads();
            bool lower = ((tid & j) == 0);
            float mn = fminf(v, other), mx = fmaxf(v, other);
            v = (lower == dir_up) ? mn : mx;
        }
        int j0 = (k >> 1 < 32) ? (k >> 1) : 16;
        for (int j = j0; j > 0; j >>= 1) {
            float other = __shfl_xor_sync(0xFFFFFFFFu, v, j);
            bool lower = ((tid & j) == 0);
            float mn = fminf(v, other), mx = fmaxf(v, other);
            v = (lower == dir_up) ? mn : mx;
        }
    }
    sort_s[tid] = v;
    __syncthreads();

    float T = sort_s[DROPK - 1];                 // largest dropped value
    if (sort_s[tid] == T && (tid == 0 || sort_s[tid - 1] < T)) c_sh = tid;
    __syncthreads();

    float wb;
    if (T == 0.f) {
        wb = w;                                  // zero gating identical either way
    } else if (w < T) {
        wb = 0.f;
    } else if (w > T) {
        wb = w;
    } else {
        // Exact tie at T>0: stable rank — drop first (DROPK - c_sh) ties by index.
        int ndrop_ties = DROPK - c_sh;
        int t = 0;
        for (int j = 0; j < tid; j++) t += (w_s[j] == T);
        wb = (t < ndrop_ties) ? 0.f : w;
    }
    g_wb[i] = wb;
}

// ---------------------------------------------------------------------------
// K4: gate (unchanged, measured at its write floor). One warp per node,
// 4 float4 per lane; wv warp-uniform, feature read skipped when wv == 0.
// ---------------------------------------------------------------------------
__global__ __launch_bounds__(256) void k4_gate(
    const float4* __restrict__ feat, float4* __restrict__ out)
{
    int gt   = blockIdx.x * blockDim.x + threadIdx.x;
    int node = gt >> 5;
    int lane = gt & 31;
    float wv = g_wb[node];
    size_t base = (size_t)node * (DD / 4) + lane;
    if (wv != 0.f) {
        float4 f0 = feat[base];
        float4 f1 = feat[base + 32];
        float4 f2 = feat[base + 64];
        float4 f3 = feat[base + 96];
        out[base]      = make_float4(f0.x*wv, f0.y*wv, f0.z*wv, f0.w*wv);
        out[base + 32] = make_float4(f1.x*wv, f1.y*wv, f1.z*wv, f1.w*wv);
        out[base + 64] = make_float4(f2.x*wv, f2.y*wv, f2.z*wv, f2.w*wv);
        out[base + 96] = make_float4(f3.x*wv, f3.y*wv, f3.z*wv, f3.w*wv);
    } else {
        float4 z = make_float4(0.f, 0.f, 0.f, 0.f);
        out[base]      = z;
        out[base + 32] = z;
        out[base + 64] = z;
        out[base + 96] = z;
    }
}

// ---------------------------------------------------------------------------
extern "C" void kernel_launch(void* const* d_in, const int* in_sizes, int n_in,
                              void* d_out, int out_size) {
    const float* features = (const float*)d_in[0];
    const void*  src      = d_in[1];
    const void*  dst      = d_in[2];
    const float* weight   = (const float*)d_in[3];
    const float* bias     = (const float*)d_in[4];
    float*       out      = (float*)d_out;

    k1_deg_matvec<<<NSPLITB + NN / 16, 256>>>(
        (const float4*)features, (const float4*)weight, dst,
        (const unsigned int*)src);

    k2_scatter<<<NSPLITB, 1024>>>(src, dst, (const unsigned int*)src);

    k3_finalize<<<BG, 1024>>>(bias);

    k4_gate<<<(NN * 32) / 256, 256>>>((const float4*)features, (float4*)out);
}

// round 12
// speedup vs baseline: 1.1557x; 1.1557x over previous
#include <cuda_runtime.h>
#include <cuda_bf16.h>

#define NN    65536
#define BG    64
#define NPG   1024
#define DD    512
#define DEG   32
#define EPG   (NPG*DEG)
#define EE    (BG*EPG)
#define DROPK 512
#define SPLIT 8                  // split-CTAs per graph for edge passes
#define NSPLITB (BG*SPLIT)       // 512
#define ECTA  (EPG/SPLIT)        // 4096 edges per split block

// Device scratch (no allocation allowed)
__device__ float g_h[NN];
__device__ int   g_deg_part[NSPLITB * NPG];
__device__ float g_agg_part[NSPLITB * NPG];
__device__ float g_wb[NN];

// int64 vs int32 edge-word probe (3 odd-word reads; L2-hot after first block).
__device__ __forceinline__ bool edges_are_i64(const unsigned int* p) {
    return (p[32769] == 0u) && (p[98305] == 0u) && (p[163841] == 0u);
}

// ---------------------------------------------------------------------------
// K1: fused. Blocks [0,512): per-split in-degree histograms. Blocks
// [512, 512+4096): matvec h = feat @ w, two rows per warp. Deg's ATOMS work
// hides under the matvec DRAM stream.
// ---------------------------------------------------------------------------
__global__ __launch_bounds__(256) void k1_deg_matvec(
    const float4* __restrict__ feat, const float4* __restrict__ w,
    const void* __restrict__ dst_p, const unsigned int* __restrict__ src_raw)
{
    __shared__ __align__(16) unsigned char sm_raw[NPG * 4];   // 4 KB

    if (blockIdx.x < NSPLITB) {
        int* deg_s = (int*)sm_raw;
        const int tid = threadIdx.x;
        const bool is64 = edges_are_i64(src_raw);
        #pragma unroll
        for (int r = 0; r < 4; r++) deg_s[r * 256 + tid] = 0;
        __syncthreads();
        const long ebase = (long)blockIdx.x * ECTA;
        #pragma unroll
        for (int r = 0; r < ECTA / 256; r++) {      // 16 iters
            long e = ebase + r * 256 + tid;
            int d = is64 ? ((const int2*)dst_p)[e].x
                         : ((const int*)dst_p)[e];
            atomicAdd(&deg_s[d & (NPG - 1)], 1);
        }
        __syncthreads();
        int* part = g_deg_part + (size_t)blockIdx.x * NPG;
        #pragma unroll
        for (int r = 0; r < 4; r++) {
            int i = r * 256 + tid;
            part[i] = deg_s[i];
        }
    } else {
        float4* w_s = (float4*)sm_raw;              // 128 float4 = 2 KB
        if (threadIdx.x < DD / 4)
            w_s[threadIdx.x] = w[threadIdx.x];
        __syncthreads();

        int warp  = ((blockIdx.x - NSPLITB) * 256 + threadIdx.x) >> 5;
        int lane  = threadIdx.x & 31;
        int row0i = warp * 2;
        const float4* row0 = feat + (size_t)row0i * (DD / 4);
        const float4* row1 = row0 + (DD / 4);

        float4 a0 = row0[lane];      float4 a1 = row0[lane + 32];
        float4 a2 = row0[lane + 64]; float4 a3 = row0[lane + 96];
        float4 b0 = row1[lane];      float4 b1 = row1[lane + 32];
        float4 b2 = row1[lane + 64]; float4 b3 = row1[lane + 96];

        float4 w0 = w_s[lane];      float4 w1 = w_s[lane + 32];
        float4 w2 = w_s[lane + 64]; float4 w3 = w_s[lane + 96];

        float s0 = a0.x*w0.x + a0.y*w0.y + a0.z*w0.z + a0.w*w0.w
                 + a1.x*w1.x + a1.y*w1.y + a1.z*w1.z + a1.w*w1.w
                 + a2.x*w2.x + a2.y*w2.y + a2.z*w2.z + a2.w*w2.w
                 + a3.x*w3.x + a3.y*w3.y + a3.z*w3.z + a3.w*w3.w;
        float s1 = b0.x*w0.x + b0.y*w0.y + b0.z*w0.z + b0.w*w0.w
                 + b1.x*w1.x + b1.y*w1.y + b1.z*w1.z + b1.w*w1.w
                 + b2.x*w2.x + b2.y*w2.y + b2.z*w2.z + b2.w*w2.w
                 + b3.x*w3.x + b3.y*w3.y + b3.z*w3.z + b3.w*w3.w;
        #pragma unroll
        for (int o = 16; o; o >>= 1) {
            s0 += __shfl_down_sync(0xFFFFFFFFu, s0, o);
            s1 += __shfl_down_sync(0xFFFFFFFFu, s1, o);
        }
        if (lane == 0) {
            g_h[row0i]     = s0;
            g_h[row0i + 1] = s1;
        }
    }
}

// ---------------------------------------------------------------------------
// K2: scatter (PDL secondary). Edge loads + agg_s zeroing run BEFORE the grid
// dependency sync -> they overlap K1's tail. Then hn reconstruction and the
// shared-atomic scatter (the measured-12.5us floor path) run after the sync.
// ---------------------------------------------------------------------------
__global__ __launch_bounds__(1024) void k2_scatter(
    const void* __restrict__ src_p, const void* __restrict__ dst_p,
    const unsigned int* __restrict__ src_raw)
{
    __shared__ float hn_s[NPG];
    __shared__ float agg_s[NPG];
    const int tid = threadIdx.x;
    const int g   = blockIdx.x >> 3;            // SPLIT = 8
    const bool is64 = edges_are_i64(src_raw);

    agg_s[tid] = 0.f;

    // ---- pre-sync: load this block's 4096 edges (independent of K1) ----
    const long ebase = (long)blockIdx.x * ECTA;
    int sv[ECTA / NPG], dv[ECTA / NPG];
    if (is64) {
        #pragma unroll
        for (int r = 0; r < ECTA / NPG; r++) {
            long e = ebase + r * NPG + tid;
            sv[r] = ((const int2*)src_p)[e].x;
            dv[r] = ((const int2*)dst_p)[e].x;
        }
    } else {
        #pragma unroll
        for (int r = 0; r < ECTA / NPG; r++) {
            long e = ebase + r * NPG + tid;
            sv[r] = ((const int*)src_p)[e];
            dv[r] = ((const int*)dst_p)[e];
        }
    }

    cudaGridDependencySynchronize();            // wait for K1 results

    {
        int dg = 0;
        #pragma unroll
        for (int s = 0; s < SPLIT; s++)
            dg += g_deg_part[(size_t)(g * SPLIT + s) * NPG + tid];
        float h = g_h[g * NPG + tid];
        hn_s[tid] = (dg > 0) ? h * rsqrtf((float)dg) : 0.f;
    }
    __syncthreads();

    #pragma unroll
    for (int r = 0; r < ECTA / NPG; r++)
        atomicAdd(&agg_s[dv[r] & (NPG - 1)], hn_s[sv[r] & (NPG - 1)]);
    __syncthreads();
    g_agg_part[(size_t)blockIdx.x * NPG + tid] = agg_s[tid];
}

// ---------------------------------------------------------------------------
// K3: finalize per graph (PDL secondary): sum partials, w = relu(agg*norm +
// bias), hybrid bitonic, threshold mask -> wb.
// ---------------------------------------------------------------------------
__global__ __launch_bounds__(1024) void k3_finalize(const float* __restrict__ bias)
{
    __shared__ float sort_s[NPG];
    __shared__ float w_s[NPG];
    __shared__ int   c_sh;

    const int g   = blockIdx.x;
    const int tid = threadIdx.x;

    cudaGridDependencySynchronize();            // wait for K2 partials

    float agg = 0.f;
    int   dg  = 0;
    #pragma unroll
    for (int s = 0; s < SPLIT; s++) {
        size_t p = (size_t)(g * SPLIT + s) * NPG + tid;
        agg += g_agg_part[p];
        dg  += g_deg_part[p];
    }
    float nm = (dg > 0) ? rsqrtf((float)dg) : 0.f;
    float w  = fmaxf(agg * nm + bias[0], 0.f);
    w_s[tid] = w;
    float v  = w;

    // Bitonic sort ascending; shared only for cross-warp stages.
    for (int k = 2; k <= NPG; k <<= 1) {
        bool dir_up = ((tid & k) == 0);
        for (int j = k >> 1; j >= 32; j >>= 1) {
            sort_s[tid] = v;
            __syncthreads();
            float other = sort_s[tid ^ j];
            __syncthreads();
            bool lower = ((tid & j) == 0);
            float mn = fminf(v, other), mx = fmaxf(v, other);
            v = (lower == dir_up) ? mn : mx;
        }
        int j0 = (k >> 1 < 32) ? (k >> 1) : 16;
        for (int j = j0; j > 0; j >>= 1) {
            float other = __shfl_xor_sync(0xFFFFFFFFu, v, j);
            bool lower = ((tid & j) == 0);
            float mn = fminf(v, other), mx = fmaxf(v, other);
            v = (lower == dir_up) ? mn : mx;
        }
    }
    sort_s[tid] = v;
    __syncthreads();

    float T = sort_s[DROPK - 1];                 // largest dropped value
    if (sort_s[tid] == T && (tid == 0 || sort_s[tid - 1] < T)) c_sh = tid;
    __syncthreads();

    float wb;
    if (T == 0.f) {
        wb = w;                                  // zero gating identical either way
    } else if (w < T) {
        wb = 0.f;
    } else if (w > T) {
        wb = w;
    } else {
        // Exact tie at T>0: stable rank — drop first (DROPK - c_sh) ties by index.
        int ndrop_ties = DROPK - c_sh;
        int t = 0;
        for (int j = 0; j < tid; j++) t += (w_s[j] == T);
        wb = (t < ndrop_ties) ? 0.f : w;
    }
    g_wb[g * NPG + tid] = wb;
}

// ---------------------------------------------------------------------------
// K4: gate (PDL secondary; body identical to the measured write-floor
// version). One warp per node, 4 float4 per lane; wv warp-uniform, feature
// read skipped when wv == 0.
// ---------------------------------------------------------------------------
__global__ __launch_bounds__(256) void k4_gate(
    const float4* __restrict__ feat, float4* __restrict__ out)
{
    int gt   = blockIdx.x * blockDim.x + threadIdx.x;
    int node = gt >> 5;
    int lane = gt & 31;
    size_t base = (size_t)node * (DD / 4) + lane;

    cudaGridDependencySynchronize();            // wait for K3's wb

    float wv = g_wb[node];
    if (wv != 0.f) {
        float4 f0 = feat[base];
        float4 f1 = feat[base + 32];
        float4 f2 = feat[base + 64];
        float4 f3 = feat[base + 96];
        out[base]      = make_float4(f0.x*wv, f0.y*wv, f0.z*wv, f0.w*wv);
        out[base + 32] = make_float4(f1.x*wv, f1.y*wv, f1.z*wv, f1.w*wv);
        out[base + 64] = make_float4(f2.x*wv, f2.y*wv, f2.z*wv, f2.w*wv);
        out[base + 96] = make_float4(f3.x*wv, f3.y*wv, f3.z*wv, f3.w*wv);
    } else {
        float4 z = make_float4(0.f, 0.f, 0.f, 0.f);
        out[base]      = z;
        out[base + 32] = z;
        out[base + 64] = z;
        out[base + 96] = z;
    }
}

// ---------------------------------------------------------------------------
// Launch helper: secondary kernels go out with the programmatic-stream-
// serialization attribute so their prologues overlap the predecessor's tail.
// ---------------------------------------------------------------------------
template <typename... Args>
static void launch_pdl(void (*kern)(Args...), dim3 grid, dim3 block,
                       Args... args)
{
    cudaLaunchConfig_t cfg = {};
    cfg.gridDim  = grid;
    cfg.blockDim = block;
    cfg.stream   = 0;
    cudaLaunchAttribute attr[1];
    attr[0].id = cudaLaunchAttributeProgrammaticStreamSerialization;
    attr[0].val.programmaticStreamSerializationAllowed = 1;
    cfg.attrs    = attr;
    cfg.numAttrs = 1;
    cudaLaunchKernelEx(&cfg, kern, args...);
}

extern "C" void kernel_launch(void* const* d_in, const int* in_sizes, int n_in,
                              void* d_out, int out_size) {
    const float* features = (const float*)d_in[0];
    const void*  src      = d_in[1];
    const void*  dst      = d_in[2];
    const float* weight   = (const float*)d_in[3];
    const float* bias     = (const float*)d_in[4];
    float*       out      = (float*)d_out;

    k1_deg_matvec<<<NSPLITB + NN / 16, 256>>>(
        (const float4*)features, (const float4*)weight, dst,
        (const unsigned int*)src);

    launch_pdl(k2_scatter, dim3(NSPLITB), dim3(1024),
               src, dst, (const unsigned int*)src);

    launch_pdl(k3_finalize, dim3(BG), dim3(1024), bias);

    launch_pdl(k4_gate, dim3((NN * 32) / 256), dim3(256),
               (const float4*)features, (float4*)out);
}

// round 15
// speedup vs baseline: 1.1818x; 1.0226x over previous
#include <cuda_runtime.h>
#include <cuda_bf16.h>

#define NN    65536
#define BG    64
#define NPG   1024
#define DD    512
#define DEG   32
#define EPG   (NPG*DEG)
#define EE    (BG*EPG)
#define DROPK 512
#define SPLIT 8                  // split-CTAs per graph for edge passes
#define NSPLITB (BG*SPLIT)       // 512
#define ECTA  (EPG/SPLIT)        // 4096 edges per split block

// Device scratch (no allocation allowed)
__device__ float g_h[NN];
__device__ int   g_deg_part[NSPLITB * NPG];
__device__ float g_agg_part[NSPLITB * NPG];
__device__ float g_wb[NN];

// int64 vs int32 edge-word probe (3 odd-word reads; L2-hot after first block).
__device__ __forceinline__ bool edges_are_i64(const unsigned int* p) {
    return (p[32769] == 0u) && (p[98305] == 0u) && (p[163841] == 0u);
}

// ---------------------------------------------------------------------------
// K1: fused. Blocks [0,512): per-split in-degree histograms with edge loads
// batched into registers (MLP 16) before the shared atomics. Blocks
// [512, 512+4096): matvec h = feat @ w, two rows per warp.
// ---------------------------------------------------------------------------
__global__ __launch_bounds__(256) void k1_deg_matvec(
    const float4* __restrict__ feat, const float4* __restrict__ w,
    const void* __restrict__ dst_p, const unsigned int* __restrict__ src_raw)
{
    __shared__ __align__(16) unsigned char sm_raw[NPG * 4];   // 4 KB

    if (blockIdx.x < NSPLITB) {
        int* deg_s = (int*)sm_raw;
        const int tid = threadIdx.x;
        const bool is64 = edges_are_i64(src_raw);
        #pragma unroll
        for (int r = 0; r < 4; r++) deg_s[r * 256 + tid] = 0;

        const long ebase = (long)blockIdx.x * ECTA;
        int dvv[16];
        if (is64) {
            #pragma unroll
            for (int r = 0; r < 16; r++)
                dvv[r] = ((const int2*)dst_p)[ebase + r * 256 + tid].x;
        } else {
            #pragma unroll
            for (int r = 0; r < 16; r++)
                dvv[r] = ((const int*)dst_p)[ebase + r * 256 + tid];
        }
        __syncthreads();
        #pragma unroll
        for (int r = 0; r < 16; r++)
            atomicAdd(&deg_s[dvv[r] & (NPG - 1)], 1);
        __syncthreads();
        int* part = g_deg_part + (size_t)blockIdx.x * NPG;
        #pragma unroll
        for (int r = 0; r < 4; r++) {
            int i = r * 256 + tid;
            part[i] = deg_s[i];
        }
    } else {
        float4* w_s = (float4*)sm_raw;              // 128 float4 = 2 KB
        if (threadIdx.x < DD / 4)
            w_s[threadIdx.x] = w[threadIdx.x];
        __syncthreads();

        int warp  = ((blockIdx.x - NSPLITB) * 256 + threadIdx.x) >> 5;
        int lane  = threadIdx.x & 31;
        int row0i = warp * 2;
        const float4* row0 = feat + (size_t)row0i * (DD / 4);
        const float4* row1 = row0 + (DD / 4);

        float4 a0 = row0[lane];      float4 a1 = row0[lane + 32];
        float4 a2 = row0[lane + 64]; float4 a3 = row0[lane + 96];
        float4 b0 = row1[lane];      float4 b1 = row1[lane + 32];
        float4 b2 = row1[lane + 64]; float4 b3 = row1[lane + 96];

        float4 w0 = w_s[lane];      float4 w1 = w_s[lane + 32];
        float4 w2 = w_s[lane + 64]; float4 w3 = w_s[lane + 96];

        float s0 = a0.x*w0.x + a0.y*w0.y + a0.z*w0.z + a0.w*w0.w
                 + a1.x*w1.x + a1.y*w1.y + a1.z*w1.z + a1.w*w1.w
                 + a2.x*w2.x + a2.y*w2.y + a2.z*w2.z + a2.w*w2.w
                 + a3.x*w3.x + a3.y*w3.y + a3.z*w3.z + a3.w*w3.w;
        float s1 = b0.x*w0.x + b0.y*w0.y + b0.z*w0.z + b0.w*w0.w
                 + b1.x*w1.x + b1.y*w1.y + b1.z*w1.z + b1.w*w1.w
                 + b2.x*w2.x + b2.y*w2.y + b2.z*w2.z + b2.w*w2.w
                 + b3.x*w3.x + b3.y*w3.y + b3.z*w3.z + b3.w*w3.w;
        #pragma unroll
        for (int o = 16; o; o >>= 1) {
            s0 += __shfl_down_sync(0xFFFFFFFFu, s0, o);
            s1 += __shfl_down_sync(0xFFFFFFFFu, s1, o);
        }
        if (lane == 0) {
            g_h[row0i]     = s0;
            g_h[row0i + 1] = s1;
        }
    }
}

// ---------------------------------------------------------------------------
// K2: scatter (measured-floor path). 512 blocks x 1024 threads: reconstruct
// hn into shared, batched edge loads, shared-atomic scatter, non-atomic
// partial writeback.
// ---------------------------------------------------------------------------
__global__ __launch_bounds__(1024) void k2_scatter(
    const void* __restrict__ src_p, const void* __restrict__ dst_p,
    const unsigned int* __restrict__ src_raw)
{
    __shared__ float hn_s[NPG];
    __shared__ float agg_s[NPG];
    const int tid = threadIdx.x;
    const int g   = blockIdx.x >> 3;            // SPLIT = 8
    const bool is64 = edges_are_i64(src_raw);

    {
        int dg = 0;
        #pragma unroll
        for (int s = 0; s < SPLIT; s++)
            dg += g_deg_part[(size_t)(g * SPLIT + s) * NPG + tid];
        float h = g_h[g * NPG + tid];
        hn_s[tid]  = (dg > 0) ? h * rsqrtf((float)dg) : 0.f;
        agg_s[tid] = 0.f;
    }
    __syncthreads();

    const long ebase = (long)blockIdx.x * ECTA;
    int sv[ECTA / NPG], dv[ECTA / NPG];
    if (is64) {
        #pragma unroll
        for (int r = 0; r < ECTA / NPG; r++) {
            long e = ebase + r * NPG + tid;
            sv[r] = ((const int2*)src_p)[e].x;
            dv[r] = ((const int2*)dst_p)[e].x;
        }
    } else {
        #pragma unroll
        for (int r = 0; r < ECTA / NPG; r++) {
            long e = ebase + r * NPG + tid;
            sv[r] = ((const int*)src_p)[e];
            dv[r] = ((const int*)dst_p)[e];
        }
    }
    #pragma unroll
    for (int r = 0; r < ECTA / NPG; r++)
        atomicAdd(&agg_s[dv[r] & (NPG - 1)], hn_s[sv[r] & (NPG - 1)]);
    __syncthreads();
    g_agg_part[(size_t)blockIdx.x * NPG + tid] = agg_s[tid];
}

// ---------------------------------------------------------------------------
// K3: finalize per graph via 4-pass byte-radix SELECT (not a sort).
// w >= 0 so float bits are order-preserving as uint. Finds T = DROPK-th
// smallest and cnt_lt = count(w < T); mask matches the bitonic version
// exactly (cnt_lt == old c_sh).
// ---------------------------------------------------------------------------
__global__ __launch_bounds__(1024) void k3_finalize(const float* __restrict__ bias)
{
    __shared__ float    w_s[NPG];
    __shared__ unsigned hist[256];
    __shared__ unsigned sel_bin_sh;
    __shared__ unsigned cntlt_sh;

    const int g   = blockIdx.x;
    const int tid = threadIdx.x;

    float agg = 0.f;
    int   dg  = 0;
    #pragma unroll
    for (int s = 0; s < SPLIT; s++) {
        size_t p = (size_t)(g * SPLIT + s) * NPG + tid;
        agg += g_agg_part[p];
        dg  += g_deg_part[p];
    }
    float nm = (dg > 0) ? rsqrtf((float)dg) : 0.f;
    float w  = fmaxf(agg * nm + bias[0], 0.f);
    w_s[tid] = w;
    unsigned key = __float_as_uint(w);
    if (tid == 0) cntlt_sh = 0;

    unsigned prefix = 0, pmask = 0;
    #pragma unroll
    for (int shift = 24; shift >= 0; shift -= 8) {
        if (tid < 256) hist[tid] = 0;
        __syncthreads();
        if ((key & pmask) == prefix)
            atomicAdd(&hist[(key >> shift) & 255u], 1u);
        __syncthreads();
        if (tid < 32) {
            unsigned need = DROPK - cntlt_sh;      // rank within active set
            unsigned local[8];
            unsigned s = 0;
            #pragma unroll
            for (int i = 0; i < 8; i++) { local[i] = hist[tid * 8 + i]; s += local[i]; }
            unsigned cum = s;
            #pragma unroll
            for (int o = 1; o < 32; o <<= 1) {
                unsigned t = __shfl_up_sync(0xFFFFFFFFu, cum, o);
                if (tid >= o) cum += t;
            }
            unsigned m    = __ballot_sync(0xFFFFFFFFu, cum >= need);
            int      lsel = __ffs(m) - 1;
            if (tid == lsel) {
                unsigned before = cum - s;         // active keys in earlier lanes
                int b = tid * 8;
                #pragma unroll
                for (int i = 0; i < 8; i++) {
                    if (before + local[i] >= need) { b = tid * 8 + i; break; }
                    before += local[i];
                }
                sel_bin_sh = (unsigned)b;
                cntlt_sh   = cntlt_sh + before;    // keys strictly below chosen bin
            }
        }
        __syncthreads();
        prefix |= sel_bin_sh << shift;
        pmask  |= 0xFFu << shift;
        __syncthreads();                            // hist reads done before next clear
    }

    float    T      = __uint_as_float(prefix);     // DROPK-th smallest
    unsigned cnt_lt = cntlt_sh;

    float wb;
    if (T == 0.f) {
        wb = w;                                    // zero gating identical either way
    } else if (w < T) {
        wb = 0.f;
    } else if (w > T) {
        wb = w;
    } else {
        // Exact tie at T>0: stable rank — drop first (DROPK - cnt_lt) ties by index.
        int ndrop_ties = DROPK - (int)cnt_lt;
        int t = 0;
        for (int j = 0; j < tid; j++) t += (w_s[j] == T);
        wb = (t < ndrop_ties) ? 0.f : w;
    }
    g_wb[g * NPG + tid] = wb;
}

// ---------------------------------------------------------------------------
// K4: gate (unchanged, at its write floor). One warp per node, 4 float4 per
// lane; wv warp-uniform, feature read skipped when wv == 0.
// ---------------------------------------------------------------------------
__global__ __launch_bounds__(256) void k4_gate(
    const float4* __restrict__ feat, float4* __restrict__ out)
{
    int gt   = blockIdx.x * blockDim.x + threadIdx.x;
    int node = gt >> 5;
    int lane = gt & 31;
    float wv = g_wb[node];
    size_t base = (size_t)node * (DD / 4) + lane;
    if (wv != 0.f) {
        float4 f0 = feat[base];
        float4 f1 = feat[base + 32];
        float4 f2 = feat[base + 64];
        float4 f3 = feat[base + 96];
        out[base]      = make_float4(f0.x*wv, f0.y*wv, f0.z*wv, f0.w*wv);
        out[base + 32] = make_float4(f1.x*wv, f1.y*wv, f1.z*wv, f1.w*wv);
        out[base + 64] = make_float4(f2.x*wv, f2.y*wv, f2.z*wv, f2.w*wv);
        out[base + 96] = make_float4(f3.x*wv, f3.y*wv, f3.z*wv, f3.w*wv);
    } else {
        float4 z = make_float4(0.f, 0.f, 0.f, 0.f);
        out[base]      = z;
        out[base + 32] = z;
        out[base + 64] = z;
        out[base + 96] = z;
    }
}

// ---------------------------------------------------------------------------
extern "C" void kernel_launch(void* const* d_in, const int* in_sizes, int n_in,
                              void* d_out, int out_size) {
    const float* features = (const float*)d_in[0];
    const void*  src      = d_in[1];
    const void*  dst      = d_in[2];
    const float* weight   = (const float*)d_in[3];
    const float* bias     = (const float*)d_in[4];
    float*       out      = (float*)d_out;

    k1_deg_matvec<<<NSPLITB + NN / 16, 256>>>(
        (const float4*)features, (const float4*)weight, dst,
        (const unsigned int*)src);

    k2_scatter<<<NSPLITB, 1024>>>(src, dst, (const unsigned int*)src);

    k3_finalize<<<BG, 1024>>>(bias);

    k4_gate<<<(NN * 32) / 256, 256>>>((const float4*)features, (float4*)out);
}

// round 16
// speedup vs baseline: 1.2236x; 1.0353x over previous
#include <cuda_runtime.h>
#include <cuda_bf16.h>

#define NN    65536
#define BG    64
#define NPG   1024
#define DD    512
#define DEG   32
#define EPG   (NPG*DEG)
#define EE    (BG*EPG)
#define DROPK 512
#define SPLIT 8                  // split-CTAs per graph for edge passes
#define NSPLITB (BG*SPLIT)       // 512
#define ECTA  (EPG/SPLIT)        // 4096 edges per split block

// Device scratch (no allocation allowed)
__device__ float g_h[NN];
__device__ int   g_deg_part[NSPLITB * NPG];
__device__ float g_agg_part[NSPLITB * NPG];
__device__ float g_wb[NN];
__device__ int   g_done[BG];
__device__ int   g_ready[BG];

// int64 vs int32 edge-word probe (3 odd-word reads; L2-hot after first block).
__device__ __forceinline__ bool edges_are_i64(const unsigned int* p) {
    return (p[32769] == 0u) && (p[98305] == 0u) && (p[163841] == 0u);
}

// ---------------------------------------------------------------------------
// K1: fused. Blocks [0,512): per-split in-degree histograms (batched loads)
// + flag resets. Blocks [512, 512+4096): matvec h = feat @ w, 2 rows/warp.
// ---------------------------------------------------------------------------
__global__ __launch_bounds__(256) void k1_deg_matvec(
    const float4* __restrict__ feat, const float4* __restrict__ w,
    const void* __restrict__ dst_p, const unsigned int* __restrict__ src_raw)
{
    __shared__ __align__(16) unsigned char sm_raw[NPG * 4];   // 4 KB

    if (blockIdx.x < NSPLITB) {
        int* deg_s = (int*)sm_raw;
        const int tid = threadIdx.x;
        if (blockIdx.x < BG && tid == 0) {
            g_done[blockIdx.x]  = 0;
            g_ready[blockIdx.x] = 0;
        }
        const bool is64 = edges_are_i64(src_raw);
        #pragma unroll
        for (int r = 0; r < 4; r++) deg_s[r * 256 + tid] = 0;

        const long ebase = (long)blockIdx.x * ECTA;
        int dvv[16];
        if (is64) {
            #pragma unroll
            for (int r = 0; r < 16; r++)
                dvv[r] = ((const int2*)dst_p)[ebase + r * 256 + tid].x;
        } else {
            #pragma unroll
            for (int r = 0; r < 16; r++)
                dvv[r] = ((const int*)dst_p)[ebase + r * 256 + tid];
        }
        __syncthreads();
        #pragma unroll
        for (int r = 0; r < 16; r++)
            atomicAdd(&deg_s[dvv[r] & (NPG - 1)], 1);
        __syncthreads();
        int* part = g_deg_part + (size_t)blockIdx.x * NPG;
        #pragma unroll
        for (int r = 0; r < 4; r++) {
            int i = r * 256 + tid;
            part[i] = deg_s[i];
        }
    } else {
        float4* w_s = (float4*)sm_raw;              // 128 float4 = 2 KB
        if (threadIdx.x < DD / 4)
            w_s[threadIdx.x] = w[threadIdx.x];
        __syncthreads();

        int warp  = ((blockIdx.x - NSPLITB) * 256 + threadIdx.x) >> 5;
        int lane  = threadIdx.x & 31;
        int row0i = warp * 2;
        const float4* row0 = feat + (size_t)row0i * (DD / 4);
        const float4* row1 = row0 + (DD / 4);

        float4 a0 = row0[lane];      float4 a1 = row0[lane + 32];
        float4 a2 = row0[lane + 64]; float4 a3 = row0[lane + 96];
        float4 b0 = row1[lane];      float4 b1 = row1[lane + 32];
        float4 b2 = row1[lane + 64]; float4 b3 = row1[lane + 96];

        float4 w0 = w_s[lane];      float4 w1 = w_s[lane + 32];
        float4 w2 = w_s[lane + 64]; float4 w3 = w_s[lane + 96];

        float s0 = a0.x*w0.x + a0.y*w0.y + a0.z*w0.z + a0.w*w0.w
                 + a1.x*w1.x + a1.y*w1.y + a1.z*w1.z + a1.w*w1.w
                 + a2.x*w2.x + a2.y*w2.y + a2.z*w2.z + a2.w*w2.w
                 + a3.x*w3.x + a3.y*w3.y + a3.z*w3.z + a3.w*w3.w;
        float s1 = b0.x*w0.x + b0.y*w0.y + b0.z*w0.z + b0.w*w0.w
                 + b1.x*w1.x + b1.y*w1.y + b1.z*w1.z + b1.w*w1.w
                 + b2.x*w2.x + b2.y*w2.y + b2.z*w2.z + b2.w*w2.w
                 + b3.x*w3.x + b3.y*w3.y + b3.z*w3.z + b3.w*w3.w;
        #pragma unroll
        for (int o = 16; o; o >>= 1) {
            s0 += __shfl_down_sync(0xFFFFFFFFu, s0, o);
            s1 += __shfl_down_sync(0xFFFFFFFFu, s1, o);
        }
        if (lane == 0) {
            g_h[row0i]     = s0;
            g_h[row0i + 1] = s1;
        }
    }
}

// ---------------------------------------------------------------------------
// K2: scatter (measured-floor path) + per-graph completion counters + early
// PDL trigger so K3K4 can start placing blocks while K2 still runs.
// ---------------------------------------------------------------------------
__global__ __launch_bounds__(1024) void k2_scatter(
    const void* __restrict__ src_p, const void* __restrict__ dst_p,
    const unsigned int* __restrict__ src_raw)
{
    cudaTriggerProgrammaticLaunchCompletion();

    __shared__ float hn_s[NPG];
    __shared__ float agg_s[NPG];
    const int tid = threadIdx.x;
    const int g   = blockIdx.x >> 3;            // SPLIT = 8
    const bool is64 = edges_are_i64(src_raw);

    {
        int dg = 0;
        #pragma unroll
        for (int s = 0; s < SPLIT; s++)
            dg += g_deg_part[(size_t)(g * SPLIT + s) * NPG + tid];
        float h = g_h[g * NPG + tid];
        hn_s[tid]  = (dg > 0) ? h * rsqrtf((float)dg) : 0.f;
        agg_s[tid] = 0.f;
    }
    __syncthreads();

    const long ebase = (long)blockIdx.x * ECTA;
    int sv[ECTA / NPG], dv[ECTA / NPG];
    if (is64) {
        #pragma unroll
        for (int r = 0; r < ECTA / NPG; r++) {
            long e = ebase + r * NPG + tid;
            sv[r] = ((const int2*)src_p)[e].x;
            dv[r] = ((const int2*)dst_p)[e].x;
        }
    } else {
        #pragma unroll
        for (int r = 0; r < ECTA / NPG; r++) {
            long e = ebase + r * NPG + tid;
            sv[r] = ((const int*)src_p)[e];
            dv[r] = ((const int*)dst_p)[e];
        }
    }
    #pragma unroll
    for (int r = 0; r < ECTA / NPG; r++)
        atomicAdd(&agg_s[dv[r] & (NPG - 1)], hn_s[sv[r] & (NPG - 1)]);
    __syncthreads();
    g_agg_part[(size_t)blockIdx.x * NPG + tid] = agg_s[tid];

    // publish partial, then bump this graph's counter (release pattern)
    __threadfence();
    __syncthreads();
    if (tid == 0) atomicAdd(&g_done[g], 1);
}

// ---------------------------------------------------------------------------
// K3K4 (PDL secondary): blocks [0,64) finalize graph b (spin g_done==SPLIT,
// radix-select threshold, write wb, set g_ready). Blocks [64, 64+2048) gate
// 32 nodes each (spin g_ready[graph], then per-warp gate at the write floor).
// Finalize blocks are the lowest bids -> dispatched before gate blocks.
// ---------------------------------------------------------------------------
__global__ __launch_bounds__(1024) void k3k4_finalize_gate(
    const float* __restrict__ bias,
    const float4* __restrict__ feat, float4* __restrict__ out)
{
    const int tid = threadIdx.x;

    if (blockIdx.x < BG) {
        // ---- finalize graph g ----
        __shared__ float    w_s[NPG];
        __shared__ unsigned hist[256];
        __shared__ unsigned sel_bin_sh;
        __shared__ unsigned cntlt_sh;
        const int g = blockIdx.x;

        if (tid == 0) {
            while (((volatile int*)g_done)[g] < SPLIT) __nanosleep(64);
        }
        __syncthreads();
        __threadfence();                           // acquire partials

        float agg = 0.f;
        int   dg  = 0;
        #pragma unroll
        for (int s = 0; s < SPLIT; s++) {
            size_t p = (size_t)(g * SPLIT + s) * NPG + tid;
            agg += g_agg_part[p];
            dg  += g_deg_part[p];
        }
        float nm = (dg > 0) ? rsqrtf((float)dg) : 0.f;
        float w  = fmaxf(agg * nm + bias[0], 0.f);
        w_s[tid] = w;
        unsigned key = __float_as_uint(w);
        if (tid == 0) cntlt_sh = 0;

        unsigned prefix = 0, pmask = 0;
        #pragma unroll
        for (int shift = 24; shift >= 0; shift -= 8) {
            if (tid < 256) hist[tid] = 0;
            __syncthreads();
            if ((key & pmask) == prefix)
                atomicAdd(&hist[(key >> shift) & 255u], 1u);
            __syncthreads();
            if (tid < 32) {
                unsigned need = DROPK - cntlt_sh;
                unsigned local[8];
                unsigned s = 0;
                #pragma unroll
                for (int i = 0; i < 8; i++) { local[i] = hist[tid * 8 + i]; s += local[i]; }
                unsigned cum = s;
                #pragma unroll
                for (int o = 1; o < 32; o <<= 1) {
                    unsigned t = __shfl_up_sync(0xFFFFFFFFu, cum, o);
                    if (tid >= o) cum += t;
                }
                unsigned m    = __ballot_sync(0xFFFFFFFFu, cum >= need);
                int      lsel = __ffs(m) - 1;
                if (tid == lsel) {
                    unsigned before = cum - s;
                    int b = tid * 8;
                    #pragma unroll
                    for (int i = 0; i < 8; i++) {
                        if (before + local[i] >= need) { b = tid * 8 + i; break; }
                        before += local[i];
                    }
                    sel_bin_sh = (unsigned)b;
                    cntlt_sh   = cntlt_sh + before;
                }
            }
            __syncthreads();
            prefix |= sel_bin_sh << shift;
            pmask  |= 0xFFu << shift;
            __syncthreads();
        }

        float    T      = __uint_as_float(prefix);
        unsigned cnt_lt = cntlt_sh;

        float wb;
        if (T == 0.f) {
            wb = w;
        } else if (w < T) {
            wb = 0.f;
        } else if (w > T) {
            wb = w;
        } else {
            int ndrop_ties = DROPK - (int)cnt_lt;
            int t = 0;
            for (int j = 0; j < tid; j++) t += (w_s[j] == T);
            wb = (t < ndrop_ties) ? 0.f : w;
        }
        g_wb[g * NPG + tid] = wb;

        __threadfence();
        __syncthreads();
        if (tid == 0) ((volatile int*)g_ready)[g] = 1;
    } else {
        // ---- gate: 32 warps -> 32 nodes ----
        int gb    = blockIdx.x - BG;               // 0..2047
        int graph = gb >> 5;                       // 32 blocks per graph
        if (tid == 0) {
            while (((volatile int*)g_ready)[graph] == 0) __nanosleep(64);
        }
        __syncthreads();
        __threadfence();                           // acquire wb

        int wid  = tid >> 5;
        int lane = tid & 31;
        int node = gb * 32 + wid;
        float wv = g_wb[node];
        size_t base = (size_t)node * (DD / 4) + lane;
        if (wv != 0.f) {
            float4 f0 = feat[base];
            float4 f1 = feat[base + 32];
            float4 f2 = feat[base + 64];
            float4 f3 = feat[base + 96];
            out[base]      = make_float4(f0.x*wv, f0.y*wv, f0.z*wv, f0.w*wv);
            out[base + 32] = make_float4(f1.x*wv, f1.y*wv, f1.z*wv, f1.w*wv);
            out[base + 64] = make_float4(f2.x*wv, f2.y*wv, f2.z*wv, f2.w*wv);
            out[base + 96] = make_float4(f3.x*wv, f3.y*wv, f3.z*wv, f3.w*wv);
        } else {
            float4 z = make_float4(0.f, 0.f, 0.f, 0.f);
            out[base]      = z;
            out[base + 32] = z;
            out[base + 64] = z;
            out[base + 96] = z;
        }
    }
}

// ---------------------------------------------------------------------------
extern "C" void kernel_launch(void* const* d_in, const int* in_sizes, int n_in,
                              void* d_out, int out_size) {
    const float* features = (const float*)d_in[0];
    const void*  src      = d_in[1];
    const void*  dst      = d_in[2];
    const float* weight   = (const float*)d_in[3];
    const float* bias     = (const float*)d_in[4];
    float*       out      = (float*)d_out;

    k1_deg_matvec<<<NSPLITB + NN / 16, 256>>>(
        (const float4*)features, (const float4*)weight, dst,
        (const unsigned int*)src);

    k2_scatter<<<NSPLITB, 1024>>>(src, dst, (const unsigned int*)src);

    {   // K3K4 as PDL secondary of K2 (trigger fires once all K2 blocks start)
        cudaLaunchConfig_t cfg = {};
        cfg.gridDim  = dim3(BG + (NN / 32));       // 64 + 2048
        cfg.blockDim = dim3(1024);
        cfg.stream   = 0;
        cudaLaunchAttribute attr[1];
        attr[0].id = cudaLaunchAttributeProgrammaticStreamSerialization;
        attr[0].val.programmaticStreamSerializationAllowed = 1;
        cfg.attrs    = attr;
        cfg.numAttrs = 1;
        cudaLaunchKernelEx(&cfg, k3k4_finalize_gate,
                           bias, (const float4*)features, (float4*)out);
    }
}